// round 16
// baseline (speedup 1.0000x reference)
#include <cuda_runtime.h>
#include <math.h>

#define LL1 1024
#define CC 384
#define HH 12
#define PP 128

#define SCALAR_W 0.14433756729740643f
#define POINT_WC 0.13608276348795434f
#define PAIR_W   0.5773502691896258f

#define PROJ 1152
#define FEAT 2112
#define KSPLIT 12
#define KSLICE 176   /* 11 * 16 */

// ------------- static scratch -------------
__device__ float g_proj[LL1 * PROJ];
__device__ float g_q   [LL1 * 192];
__device__ float g_kT  [HH * 16 * LL1];
__device__ float g_vT  [HH * 16 * LL1];
__device__ float g_qp  [LL1 * 144];
__device__ float g_kpT [HH * 12 * LL1];
__device__ float g_vpT [HH * 24 * LL1];
__device__ float g_sqq [HH * LL1];
__device__ float g_sqk [HH * LL1];
__device__ float g_Z   [(size_t)HH * LL1 * LL1];  // qk logits -> (+pair) -> attn
__device__ float g_feat[(size_t)LL1 * FEAT];
__device__ float g_part[KSPLIT * LL1 * CC];

// ------------- K1: projection GEMM, 32x128 tiles -------------
__device__ __forceinline__ float wload(int r, int gc, const float* Wq,
    const float* Wkv, const float* Wqp, const float* Wkvp) {
  if (gc < 192) return Wq[r * 192 + gc];
  if (gc < 576) return Wkv[r * 384 + (gc - 192)];
  if (gc < 720) return Wqp[r * 144 + (gc - 576)];
  return Wkvp[r * 432 + (gc - 720)];
}

__global__ __launch_bounds__(256) void k_projgemm(const float* __restrict__ x1d,
    const float* __restrict__ Wq, const float* __restrict__ Wkv,
    const float* __restrict__ Wqp, const float* __restrict__ Wkvp) {
  __shared__ float s_x[16][36];
  __shared__ float s_w[16][128];
  int tid = threadIdx.x;
  int tx = tid & 15, ty = tid >> 4;
  int i0 = blockIdx.x * 32, c0 = blockIdx.y * 128;
  float acc[2][8] = {};
  for (int k0 = 0; k0 < CC; k0 += 16) {
    __syncthreads();
    for (int idx = tid; idx < 512; idx += 256) {
      int il = idx >> 4, kk = idx & 15;
      s_x[kk][il] = x1d[(i0 + il) * CC + k0 + kk];
    }
    for (int idx = tid; idx < 2048; idx += 256) {
      int kk = idx >> 7, cl = idx & 127;
      s_w[kk][cl] = wload(k0 + kk, c0 + cl, Wq, Wkv, Wqp, Wkvp);
    }
    __syncthreads();
#pragma unroll
    for (int kk = 0; kk < 16; kk++) {
      float xv[2], wv[8];
#pragma unroll
      for (int r = 0; r < 2; r++) xv[r] = s_x[kk][ty * 2 + r];
#pragma unroll
      for (int c = 0; c < 8; c++) wv[c] = s_w[kk][tx * 8 + c];
#pragma unroll
      for (int r = 0; r < 2; r++)
#pragma unroll
        for (int c = 0; c < 8; c++) acc[r][c] += xv[r] * wv[c];
    }
  }
#pragma unroll
  for (int r = 0; r < 2; r++)
#pragma unroll
    for (int c = 0; c < 8; c++)
      g_proj[(size_t)(i0 + ty * 2 + r) * PROJ + c0 + tx * 8 + c] = acc[r][c];
}

// ------------- K2: bias/split/rigid/norms -------------
__global__ void k_post(const float* __restrict__ rot, const float* __restrict__ trans,
                       const float* __restrict__ bq, const float* __restrict__ bkv,
                       const float* __restrict__ bqp, const float* __restrict__ bkvp) {
  int i = blockIdx.x, tid = threadIdx.x;
  __shared__ float s_R[9], s_t[3], s_pt[96][3];
  if (tid < 9) s_R[tid] = rot[i * 9 + tid];
  else if (tid < 12) s_t[tid - 9] = trans[i * 3 + tid - 9];
  __syncthreads();
  const float* pr = &g_proj[(size_t)i * PROJ];
  for (int idx = tid; idx < 576; idx += 256) {
    if (idx < 192) {
      g_q[(size_t)i * 192 + idx] = (pr[idx] + bq[idx]) * SCALAR_W;
    } else {
      int m = idx - 192, hh = m >> 5, t = m & 31;
      float v = pr[idx] + bkv[m];
      if (t < 16) g_kT[(hh * 16 + t) * LL1 + i] = v;
      else        g_vT[(hh * 16 + t - 16) * LL1 + i] = v;
    }
  }
  for (int m = tid; m < 192; m += 256) {
    float p0, p1, p2;
    if (m < 48) {
      p0 = pr[576 + m] + bqp[m];
      p1 = pr[624 + m] + bqp[48 + m];
      p2 = pr[672 + m] + bqp[96 + m];
    } else {
      int mm = m - 48;
      p0 = pr[720 + mm] + bkvp[mm];
      p1 = pr[864 + mm] + bkvp[144 + mm];
      p2 = pr[1008 + mm] + bkvp[288 + mm];
    }
    float gx = s_R[0] * p0 + s_R[1] * p1 + s_R[2] * p2 + s_t[0];
    float gy = s_R[3] * p0 + s_R[4] * p1 + s_R[5] * p2 + s_t[1];
    float gz = s_R[6] * p0 + s_R[7] * p1 + s_R[8] * p2 + s_t[2];
    if (m < 48) {
      int hh = m >> 2, n = m & 3;
      size_t b = (size_t)i * 144 + hh * 12 + n * 3;
      g_qp[b] = gx; g_qp[b + 1] = gy; g_qp[b + 2] = gz;
      s_pt[m][0] = gx; s_pt[m][1] = gy; s_pt[m][2] = gz;
    } else {
      int mm = m - 48, hh = mm / 12, t = mm % 12;
      if (t < 4) {
        int b = (hh * 12 + t * 3) * LL1 + i;
        g_kpT[b] = gx; g_kpT[b + LL1] = gy; g_kpT[b + 2 * LL1] = gz;
        int sp = 48 + hh * 4 + t;
        s_pt[sp][0] = gx; s_pt[sp][1] = gy; s_pt[sp][2] = gz;
      } else {
        int b = (hh * 24 + (t - 4) * 3) * LL1 + i;
        g_vpT[b] = gx; g_vpT[b + LL1] = gy; g_vpT[b + 2 * LL1] = gz;
      }
    }
  }
  __syncthreads();
  if (tid < 24) {
    int hh = tid % 12; bool isq = tid < 12;
    float s = 0.f;
#pragma unroll
    for (int n = 0; n < 4; n++) {
      const float* p = s_pt[(isq ? 0 : 48) + hh * 4 + n];
      s += p[0] * p[0] + p[1] * p[1] + p[2] * p[2];
    }
    if (isq) g_sqq[hh * LL1 + i] = s;
    else     g_sqk[hh * LL1 + i] = s;
  }
}

// ------------- K3: qk + dist logits -> g_Z -------------
__global__ void k_qk(const float* __restrict__ tpw) {
  int i0 = blockIdx.x * 16, h = blockIdx.y, tid = threadIdx.x;
  __shared__ float s_qT[16][16];
  __shared__ float s_qpT[12][16];
  __shared__ float s_sqq[16];
  __shared__ float s_pw;
  {
    int ii = tid >> 4, s = tid & 15;
    s_qT[s][ii] = g_q[(size_t)(i0 + ii) * 192 + h * 16 + s];
    if (tid < 192) { int r = tid % 12, ii2 = tid / 12; s_qpT[r][ii2] = g_qp[(size_t)(i0 + ii2) * 144 + h * 12 + r]; }
    if (tid < 16) s_sqq[tid] = g_sqq[h * LL1 + i0 + tid];
    if (tid == 0) {
      float x = tpw[h];
      s_pw = -0.5f * POINT_WC * (fmaxf(x, 0.f) + log1pf(expf(-fabsf(x))));
    }
  }
  __syncthreads();
  int j0 = tid * 4;
  float4 kv[16], kp[12];
#pragma unroll
  for (int s = 0; s < 16; s++) kv[s] = *(const float4*)&g_kT[(h * 16 + s) * LL1 + j0];
#pragma unroll
  for (int r = 0; r < 12; r++) kp[r] = *(const float4*)&g_kpT[(h * 12 + r) * LL1 + j0];
  float4 sqk = *(const float4*)&g_sqk[h * LL1 + j0];
  float pw = s_pw;
#pragma unroll
  for (int ii = 0; ii < 16; ii++) {
    float4 d = {0,0,0,0}, pq = {0,0,0,0};
#pragma unroll
    for (int s = 0; s < 16; s++) {
      float q = s_qT[s][ii];
      d.x += q * kv[s].x; d.y += q * kv[s].y; d.z += q * kv[s].z; d.w += q * kv[s].w;
    }
#pragma unroll
    for (int r = 0; r < 12; r++) {
      float q = s_qpT[r][ii];
      pq.x += q * kp[r].x; pq.y += q * kp[r].y; pq.z += q * kp[r].z; pq.w += q * kp[r].w;
    }
    float sq = s_sqq[ii];
    float4 o;
    o.x = d.x + pw * (sq + sqk.x - 2.f * pq.x);
    o.y = d.y + pw * (sq + sqk.y - 2.f * pq.y);
    o.z = d.z + pw * (sq + sqk.z - 2.f * pq.z);
    o.w = d.w + pw * (sq + sqk.w - 2.f * pq.w);
    *(float4*)&g_Z[((size_t)(h * LL1 + i0 + ii)) * LL1 + j0] = o;
  }
}

// ------------- K4: pair bias GEMM, += into g_Z; direct LDG, no staging -----
// block = (i, j-half of 512). 256 threads, 2 j each. No syncs in hot loop.
__global__ __launch_bounds__(256) void k_pairbias(const float* __restrict__ x2d,
    const float* __restrict__ Wp, const float* __restrict__ bp) {
  __shared__ float s_W[1536];
  __shared__ float s_b[12];
  int i = blockIdx.x, j0 = blockIdx.y * 512, tid = threadIdx.x;
  for (int t = tid; t < 1536; t += 256) s_W[t] = Wp[t];
  if (tid < 12) s_b[tid] = bp[tid];
  __syncthreads();
  const float* r0 = x2d + ((size_t)i * LL1 + j0 + tid) * PP;
  const float* r1 = r0 + 256 * PP;
  float acc0[12] = {}, acc1[12] = {};
#pragma unroll 4
  for (int k4 = 0; k4 < 32; k4++) {
    float4 x0 = *(const float4*)(r0 + k4 * 4);
    float4 x1 = *(const float4*)(r1 + k4 * 4);
#pragma unroll
    for (int c = 0; c < 4; c++) {
      int k = k4 * 4 + c;
      float a0 = (&x0.x)[c], a1 = (&x1.x)[c];
      float4 w0 = *(const float4*)&s_W[k * 12];
      float4 w1 = *(const float4*)&s_W[k * 12 + 4];
      float4 w2 = *(const float4*)&s_W[k * 12 + 8];
      acc0[0] += a0 * w0.x; acc0[1] += a0 * w0.y; acc0[2]  += a0 * w0.z; acc0[3]  += a0 * w0.w;
      acc0[4] += a0 * w1.x; acc0[5] += a0 * w1.y; acc0[6]  += a0 * w1.z; acc0[7]  += a0 * w1.w;
      acc0[8] += a0 * w2.x; acc0[9] += a0 * w2.y; acc0[10] += a0 * w2.z; acc0[11] += a0 * w2.w;
      acc1[0] += a1 * w0.x; acc1[1] += a1 * w0.y; acc1[2]  += a1 * w0.z; acc1[3]  += a1 * w0.w;
      acc1[4] += a1 * w1.x; acc1[5] += a1 * w1.y; acc1[6]  += a1 * w1.z; acc1[7]  += a1 * w1.w;
      acc1[8] += a1 * w2.x; acc1[9] += a1 * w2.y; acc1[10] += a1 * w2.z; acc1[11] += a1 * w2.w;
    }
  }
#pragma unroll
  for (int h = 0; h < 12; h++) {
    float b = s_b[h];
    size_t base = ((size_t)h * LL1 + i) * LL1 + j0 + tid;
    g_Z[base]       += PAIR_W * (acc0[h] + b);
    g_Z[base + 256] += PAIR_W * (acc1[h] + b);
  }
}

// ------------- K5: softmax per (i,h), register-resident -------------
__global__ __launch_bounds__(256) void k_softmax() {
  int i = blockIdx.x, h = blockIdx.y, tid = threadIdx.x;
  int lane = tid & 31, w = tid >> 5;
  __shared__ float s_red[8];
  __shared__ float s_bc;
  float* zr = &g_Z[((size_t)h * LL1 + i) * LL1];
  float4 v = *(const float4*)&zr[tid * 4];
  float m = fmaxf(fmaxf(v.x, v.y), fmaxf(v.z, v.w));
#pragma unroll
  for (int o = 16; o; o >>= 1) m = fmaxf(m, __shfl_xor_sync(~0u, m, o));
  if (lane == 0) s_red[w] = m;
  __syncthreads();
  if (tid == 0) {
    float mm = s_red[0];
#pragma unroll
    for (int q = 1; q < 8; q++) mm = fmaxf(mm, s_red[q]);
    s_bc = mm;
  }
  __syncthreads();
  m = s_bc;
  float4 e;
  e.x = __expf(v.x - m); e.y = __expf(v.y - m);
  e.z = __expf(v.z - m); e.w = __expf(v.w - m);
  float s = e.x + e.y + e.z + e.w;
#pragma unroll
  for (int o = 16; o; o >>= 1) s += __shfl_xor_sync(~0u, s, o);
  if (lane == 0) s_red[w] = s;
  __syncthreads();
  if (tid == 0) {
    float ss = 0.f;
#pragma unroll
    for (int q = 0; q < 8; q++) ss += s_red[q];
    s_bc = 1.f / ss;
  }
  __syncthreads();
  float inv = s_bc;
  e.x *= inv; e.y *= inv; e.z *= inv; e.w *= inv;
  *(float4*)&zr[tid * 4] = e;
}

// ------------- K6: r_2d = attn @ x2d (block = i, float4 + j-slab split) -----
__global__ __launch_bounds__(256) void k_r2d(const float* __restrict__ x2d) {
  __shared__ float s_at[12][1032];
  __shared__ float s_part[128 * 12];
  int i = blockIdx.x, tid = threadIdx.x;
  for (int idx = tid; idx < 12288; idx += 256) {
    int row = idx >> 10, col = idx & 1023;
    s_at[row][col] = g_Z[((size_t)row * LL1 + i) * LL1 + col];
  }
  __syncthreads();
  int c4 = (tid & 31) * 4;
  int hg = (tid >> 5) & 3;
  int jslab = tid >> 7;
  float4 acc[3] = {};
  const float* xr = x2d + ((size_t)i * LL1 + jslab * 512) * PP + c4;
#pragma unroll 4
  for (int jj = 0; jj < 512; jj++) {
    float4 xv = *(const float4*)(xr + (size_t)jj * PP);
#pragma unroll
    for (int hh = 0; hh < 3; hh++) {
      float a = s_at[hg * 3 + hh][jslab * 512 + jj];
      acc[hh].x += a * xv.x; acc[hh].y += a * xv.y;
      acc[hh].z += a * xv.z; acc[hh].w += a * xv.w;
    }
  }
  if (jslab == 1) {
    int p = tid - 128;
#pragma unroll
    for (int hh = 0; hh < 3; hh++)
      *(float4*)&s_part[(hh * 128 + p) * 4] = acc[hh];
  }
  __syncthreads();
  if (jslab == 0) {
    size_t base = (size_t)i * FEAT + 576;
#pragma unroll
    for (int hh = 0; hh < 3; hh++) {
      float4 o = *(const float4*)&s_part[(hh * 128 + tid) * 4];
      o.x += acc[hh].x; o.y += acc[hh].y; o.z += acc[hh].z; o.w += acc[hh].w;
      *(float4*)&g_feat[base + (hg * 3 + hh) * PP + c4] = o;
    }
  }
}

// ------------- K7: attn @ {v_s, vp} + inverse rigid + f_n -------------
__global__ void k_attnout(const float* __restrict__ rot, const float* __restrict__ trans) {
  int i0 = blockIdx.x * 8, h = blockIdx.y;
  int tid = threadIdx.x, lane = tid & 31, w = tid >> 5;
  __shared__ float s_a[8][1024];
  __shared__ float s_out[40][8];
  for (int idx = tid; idx < 8192; idx += 256) {
    int ii = idx >> 10, j = idx & 1023;
    s_a[ii][j] = g_Z[(size_t)(h * LL1 + i0 + ii) * LL1 + j];
  }
  __syncthreads();
  float acc[5][8];
#pragma unroll
  for (int c = 0; c < 5; c++)
#pragma unroll
    for (int ii = 0; ii < 8; ii++) acc[c][ii] = 0.f;
  const float* vptr[5];
#pragma unroll
  for (int c = 0; c < 5; c++) {
    int ch = w * 5 + c;
    vptr[c] = (ch < 16) ? &g_vT[(h * 16 + ch) * LL1] : &g_vpT[(h * 24 + ch - 16) * LL1];
  }
  for (int j = lane; j < 1024; j += 32) {
    float a[8];
#pragma unroll
    for (int ii = 0; ii < 8; ii++) a[ii] = s_a[ii][j];
#pragma unroll
    for (int c = 0; c < 5; c++) {
      float v = vptr[c][j];
#pragma unroll
      for (int ii = 0; ii < 8; ii++) acc[c][ii] += a[ii] * v;
    }
  }
#pragma unroll
  for (int c = 0; c < 5; c++)
#pragma unroll
    for (int ii = 0; ii < 8; ii++) {
      float s = acc[c][ii];
      for (int o = 16; o; o >>= 1) s += __shfl_xor_sync(~0u, s, o);
      if (lane == 0) s_out[w * 5 + c][ii] = s;
    }
  __syncthreads();
  if (tid < 128) {
    int ii = tid >> 4, c = tid & 15;
    g_feat[(size_t)(i0 + ii) * FEAT + h * 16 + c] = s_out[c][ii];
  } else if (tid < 192) {
    int p = tid - 128, ii = p >> 3, n = p & 7;
    int gi = i0 + ii;
    float R[9], t[3];
#pragma unroll
    for (int q = 0; q < 9; q++) R[q] = rot[gi * 9 + q];
#pragma unroll
    for (int q = 0; q < 3; q++) t[q] = trans[gi * 3 + q];
    float d0 = s_out[16 + n * 3 + 0][ii] - t[0];
    float d1 = s_out[16 + n * 3 + 1][ii] - t[1];
    float d2 = s_out[16 + n * 3 + 2][ii] - t[2];
    float lx = R[0] * d0 + R[3] * d1 + R[6] * d2;
    float ly = R[1] * d0 + R[4] * d1 + R[7] * d2;
    float lz = R[2] * d0 + R[5] * d1 + R[8] * d2;
    size_t base = (size_t)gi * FEAT;
    g_feat[base + 192 + 0 * 96 + h * 8 + n] = lx;
    g_feat[base + 192 + 1 * 96 + h * 8 + n] = ly;
    g_feat[base + 192 + 2 * 96 + h * 8 + n] = lz;
    g_feat[base + 480 + h * 8 + n] = sqrtf(lx * lx + ly * ly + lz * lz + 1e-8f);
  }
}

// ------------- K8: output GEMM, split-K x12 partials -------------
__global__ __launch_bounds__(256) void k_outpart(const float* __restrict__ Wout) {
  __shared__ float s_f[16][68];
  __shared__ float s_w[16][68];
  int tid = threadIdx.x;
  int tx = tid & 15, ty = tid >> 4;
  int i0 = blockIdx.x * 64, c0 = blockIdx.y * 64;
  int kbeg = blockIdx.z * KSLICE, kend = kbeg + KSLICE;
  float acc[4][4] = {};
  for (int k0 = kbeg; k0 < kend; k0 += 16) {
    __syncthreads();
    for (int idx = tid; idx < 1024; idx += 256) {
      int il = idx >> 4, kk = idx & 15;
      s_f[kk][il] = g_feat[(size_t)(i0 + il) * FEAT + k0 + kk];
    }
    for (int idx = tid; idx < 1024; idx += 256) {
      int kk = idx >> 6, cl = idx & 63;
      s_w[kk][cl] = Wout[(size_t)(k0 + kk) * CC + c0 + cl];
    }
    __syncthreads();
#pragma unroll
    for (int kk = 0; kk < 16; kk++) {
      float xv[4], wv[4];
#pragma unroll
      for (int r = 0; r < 4; r++) xv[r] = s_f[kk][ty * 4 + r];
#pragma unroll
      for (int c = 0; c < 4; c++) wv[c] = s_w[kk][tx * 4 + c];
#pragma unroll
      for (int r = 0; r < 4; r++)
#pragma unroll
        for (int c = 0; c < 4; c++) acc[r][c] += xv[r] * wv[c];
    }
  }
  float* part = &g_part[(size_t)blockIdx.z * LL1 * CC];
#pragma unroll
  for (int r = 0; r < 4; r++)
#pragma unroll
    for (int c = 0; c < 4; c++)
      part[(size_t)(i0 + ty * 4 + r) * CC + c0 + tx * 4 + c] = acc[r][c];
}

__global__ __launch_bounds__(256) void k_outadd(const float* __restrict__ bout,
                                                float* __restrict__ out) {
  int idx = blockIdx.x * 256 + threadIdx.x;
  float s = 0.f;
#pragma unroll
  for (int z = 0; z < KSPLIT; z++) s += g_part[(size_t)z * LL1 * CC + idx];
  out[idx] = s + bout[idx % CC];
}

// ------------- launch -------------
extern "C" void kernel_launch(void* const* d_in, const int* in_sizes, int n_in,
                              void* d_out, int out_size) {
  (void)in_sizes; (void)n_in; (void)out_size;
  const float* x1d   = (const float*)d_in[0];
  const float* x2d   = (const float*)d_in[1];
  const float* rot   = (const float*)d_in[2];
  const float* trans = (const float*)d_in[3];
  const float* Wq    = (const float*)d_in[5];
  const float* bq    = (const float*)d_in[6];
  const float* Wkv   = (const float*)d_in[7];
  const float* bkv   = (const float*)d_in[8];
  const float* Wqp   = (const float*)d_in[9];
  const float* bqp   = (const float*)d_in[10];
  const float* Wkvp  = (const float*)d_in[11];
  const float* bkvp  = (const float*)d_in[12];
  const float* Wpair = (const float*)d_in[13];
  const float* bpair = (const float*)d_in[14];
  const float* tpw   = (const float*)d_in[15];
  const float* Wout  = (const float*)d_in[16];
  const float* bout  = (const float*)d_in[17];
  float* out = (float*)d_out;

  k_projgemm<<<dim3(32, 9), 256>>>(x1d, Wq, Wkv, Wqp, Wkvp);
  k_post<<<1024, 256>>>(rot, trans, bq, bkv, bqp, bkvp);
  k_qk<<<dim3(64, 12), 256>>>(tpw);
  k_pairbias<<<dim3(1024, 2), 256>>>(x2d, Wpair, bpair);
  k_softmax<<<dim3(1024, 12), 256>>>();
  k_r2d<<<1024, 256>>>(x2d);
  k_attnout<<<dim3(128, 12), 256>>>(rot, trans);
  k_outpart<<<dim3(16, 6, KSPLIT), 256>>>(Wout);
  k_outadd<<<1536, 256>>>(bout, out);
}

// round 17
// speedup vs baseline: 1.0140x; 1.0140x over previous
#include <cuda_runtime.h>
#include <math.h>

#define LL1 1024
#define CC 384
#define HH 12
#define PP 128

#define SCALAR_W 0.14433756729740643f
#define POINT_WC 0.13608276348795434f
#define PAIR_W   0.5773502691896258f

#define PROJ 1152
#define FEAT 2112
#define KSPLIT 12
#define KSLICE 176   /* 11 * 16 */

// ------------- static scratch -------------
__device__ float g_proj[LL1 * PROJ];
__device__ float g_q   [LL1 * 192];
__device__ float g_kT  [HH * 16 * LL1];
__device__ float g_vT  [HH * 16 * LL1];
__device__ float g_qp  [LL1 * 144];
__device__ float g_kpT [HH * 12 * LL1];
__device__ float g_vpT [HH * 24 * LL1];
__device__ float g_sqq [HH * LL1];
__device__ float g_sqk [HH * LL1];
__device__ float g_Z   [(size_t)HH * LL1 * LL1];  // qk logits -> (+pair) -> attn
__device__ float g_feat[(size_t)LL1 * FEAT];
__device__ float g_part[KSPLIT * LL1 * CC];

// ------------- K1: projection GEMM, 32x128 tiles -------------
__device__ __forceinline__ float wload(int r, int gc, const float* Wq,
    const float* Wkv, const float* Wqp, const float* Wkvp) {
  if (gc < 192) return Wq[r * 192 + gc];
  if (gc < 576) return Wkv[r * 384 + (gc - 192)];
  if (gc < 720) return Wqp[r * 144 + (gc - 576)];
  return Wkvp[r * 432 + (gc - 720)];
}

__global__ __launch_bounds__(256) void k_projgemm(const float* __restrict__ x1d,
    const float* __restrict__ Wq, const float* __restrict__ Wkv,
    const float* __restrict__ Wqp, const float* __restrict__ Wkvp) {
  __shared__ float s_x[16][36];
  __shared__ float s_w[16][128];
  int tid = threadIdx.x;
  int tx = tid & 15, ty = tid >> 4;
  int i0 = blockIdx.x * 32, c0 = blockIdx.y * 128;
  float acc[2][8] = {};
  for (int k0 = 0; k0 < CC; k0 += 16) {
    __syncthreads();
    for (int idx = tid; idx < 512; idx += 256) {
      int il = idx >> 4, kk = idx & 15;
      s_x[kk][il] = x1d[(i0 + il) * CC + k0 + kk];
    }
    for (int idx = tid; idx < 2048; idx += 256) {
      int kk = idx >> 7, cl = idx & 127;
      s_w[kk][cl] = wload(k0 + kk, c0 + cl, Wq, Wkv, Wqp, Wkvp);
    }
    __syncthreads();
#pragma unroll
    for (int kk = 0; kk < 16; kk++) {
      float xv[2], wv[8];
#pragma unroll
      for (int r = 0; r < 2; r++) xv[r] = s_x[kk][ty * 2 + r];
#pragma unroll
      for (int c = 0; c < 8; c++) wv[c] = s_w[kk][tx * 8 + c];
#pragma unroll
      for (int r = 0; r < 2; r++)
#pragma unroll
        for (int c = 0; c < 8; c++) acc[r][c] += xv[r] * wv[c];
    }
  }
#pragma unroll
  for (int r = 0; r < 2; r++)
#pragma unroll
    for (int c = 0; c < 8; c++)
      g_proj[(size_t)(i0 + ty * 2 + r) * PROJ + c0 + tx * 8 + c] = acc[r][c];
}

// ------------- K2: bias/split/rigid/norms -------------
__global__ void k_post(const float* __restrict__ rot, const float* __restrict__ trans,
                       const float* __restrict__ bq, const float* __restrict__ bkv,
                       const float* __restrict__ bqp, const float* __restrict__ bkvp) {
  int i = blockIdx.x, tid = threadIdx.x;
  __shared__ float s_R[9], s_t[3], s_pt[96][3];
  if (tid < 9) s_R[tid] = rot[i * 9 + tid];
  else if (tid < 12) s_t[tid - 9] = trans[i * 3 + tid - 9];
  __syncthreads();
  const float* pr = &g_proj[(size_t)i * PROJ];
  for (int idx = tid; idx < 576; idx += 256) {
    if (idx < 192) {
      g_q[(size_t)i * 192 + idx] = (pr[idx] + bq[idx]) * SCALAR_W;
    } else {
      int m = idx - 192, hh = m >> 5, t = m & 31;
      float v = pr[idx] + bkv[m];
      if (t < 16) g_kT[(hh * 16 + t) * LL1 + i] = v;
      else        g_vT[(hh * 16 + t - 16) * LL1 + i] = v;
    }
  }
  for (int m = tid; m < 192; m += 256) {
    float p0, p1, p2;
    if (m < 48) {
      p0 = pr[576 + m] + bqp[m];
      p1 = pr[624 + m] + bqp[48 + m];
      p2 = pr[672 + m] + bqp[96 + m];
    } else {
      int mm = m - 48;
      p0 = pr[720 + mm] + bkvp[mm];
      p1 = pr[864 + mm] + bkvp[144 + mm];
      p2 = pr[1008 + mm] + bkvp[288 + mm];
    }
    float gx = s_R[0] * p0 + s_R[1] * p1 + s_R[2] * p2 + s_t[0];
    float gy = s_R[3] * p0 + s_R[4] * p1 + s_R[5] * p2 + s_t[1];
    float gz = s_R[6] * p0 + s_R[7] * p1 + s_R[8] * p2 + s_t[2];
    if (m < 48) {
      int hh = m >> 2, n = m & 3;
      size_t b = (size_t)i * 144 + hh * 12 + n * 3;
      g_qp[b] = gx; g_qp[b + 1] = gy; g_qp[b + 2] = gz;
      s_pt[m][0] = gx; s_pt[m][1] = gy; s_pt[m][2] = gz;
    } else {
      int mm = m - 48, hh = mm / 12, t = mm % 12;
      if (t < 4) {
        int b = (hh * 12 + t * 3) * LL1 + i;
        g_kpT[b] = gx; g_kpT[b + LL1] = gy; g_kpT[b + 2 * LL1] = gz;
        int sp = 48 + hh * 4 + t;
        s_pt[sp][0] = gx; s_pt[sp][1] = gy; s_pt[sp][2] = gz;
      } else {
        int b = (hh * 24 + (t - 4) * 3) * LL1 + i;
        g_vpT[b] = gx; g_vpT[b + LL1] = gy; g_vpT[b + 2 * LL1] = gz;
      }
    }
  }
  __syncthreads();
  if (tid < 24) {
    int hh = tid % 12; bool isq = tid < 12;
    float s = 0.f;
#pragma unroll
    for (int n = 0; n < 4; n++) {
      const float* p = s_pt[(isq ? 0 : 48) + hh * 4 + n];
      s += p[0] * p[0] + p[1] * p[1] + p[2] * p[2];
    }
    if (isq) g_sqq[hh * LL1 + i] = s;
    else     g_sqk[hh * LL1 + i] = s;
  }
}

// ------------- K3: qk + dist logits -> g_Z -------------
__global__ void k_qk(const float* __restrict__ tpw) {
  int i0 = blockIdx.x * 16, h = blockIdx.y, tid = threadIdx.x;
  __shared__ float s_qT[16][16];
  __shared__ float s_qpT[12][16];
  __shared__ float s_sqq[16];
  __shared__ float s_pw;
  {
    int ii = tid >> 4, s = tid & 15;
    s_qT[s][ii] = g_q[(size_t)(i0 + ii) * 192 + h * 16 + s];
    if (tid < 192) { int r = tid % 12, ii2 = tid / 12; s_qpT[r][ii2] = g_qp[(size_t)(i0 + ii2) * 144 + h * 12 + r]; }
    if (tid < 16) s_sqq[tid] = g_sqq[h * LL1 + i0 + tid];
    if (tid == 0) {
      float x = tpw[h];
      s_pw = -0.5f * POINT_WC * (fmaxf(x, 0.f) + log1pf(expf(-fabsf(x))));
    }
  }
  __syncthreads();
  int j0 = tid * 4;
  float4 kv[16], kp[12];
#pragma unroll
  for (int s = 0; s < 16; s++) kv[s] = *(const float4*)&g_kT[(h * 16 + s) * LL1 + j0];
#pragma unroll
  for (int r = 0; r < 12; r++) kp[r] = *(const float4*)&g_kpT[(h * 12 + r) * LL1 + j0];
  float4 sqk = *(const float4*)&g_sqk[h * LL1 + j0];
  float pw = s_pw;
#pragma unroll
  for (int ii = 0; ii < 16; ii++) {
    float4 d = {0,0,0,0}, pq = {0,0,0,0};
#pragma unroll
    for (int s = 0; s < 16; s++) {
      float q = s_qT[s][ii];
      d.x += q * kv[s].x; d.y += q * kv[s].y; d.z += q * kv[s].z; d.w += q * kv[s].w;
    }
#pragma unroll
    for (int r = 0; r < 12; r++) {
      float q = s_qpT[r][ii];
      pq.x += q * kp[r].x; pq.y += q * kp[r].y; pq.z += q * kp[r].z; pq.w += q * kp[r].w;
    }
    float sq = s_sqq[ii];
    float4 o;
    o.x = d.x + pw * (sq + sqk.x - 2.f * pq.x);
    o.y = d.y + pw * (sq + sqk.y - 2.f * pq.y);
    o.z = d.z + pw * (sq + sqk.z - 2.f * pq.z);
    o.w = d.w + pw * (sq + sqk.w - 2.f * pq.w);
    *(float4*)&g_Z[((size_t)(h * LL1 + i0 + ii)) * LL1 + j0] = o;
  }
}

// ------------- K4: pair bias GEMM, += into g_Z; 32-k chunks (128B/row) -----
// dyn smem floats: s_x 32*516=16512 | s_W 1536 | s_b 12 -> 18060 (72240 B)
#define PB_SMEM_BYTES (18060 * 4)

__global__ __launch_bounds__(256) void k_pairbias(const float* __restrict__ x2d,
    const float* __restrict__ Wp, const float* __restrict__ bp) {
  extern __shared__ float sm[];
  float* s_x = sm;             // 32 x 516
  float* s_W = sm + 16512;     // 1536
  float* s_b = s_W + 1536;     // 12
  int i = blockIdx.x, j0 = blockIdx.y * 512, tid = threadIdx.x;
  for (int t = tid; t < 1536; t += 256) s_W[t] = Wp[t];
  if (tid < 12) s_b[tid] = bp[tid];
  float acc0[12] = {}, acc1[12] = {};
  const float* xrow = x2d + ((size_t)i * LL1 + j0) * PP;
  for (int k0 = 0; k0 < 128; k0 += 32) {
    __syncthreads();
#pragma unroll
    for (int p = 0; p < 16; p++) {
      int idx = p * 256 + tid;
      int r = idx >> 3, qq = idx & 7;
      float4 v = *(const float4*)(xrow + (size_t)r * PP + k0 + qq * 4);
      s_x[(qq * 4 + 0) * 516 + r] = v.x;
      s_x[(qq * 4 + 1) * 516 + r] = v.y;
      s_x[(qq * 4 + 2) * 516 + r] = v.z;
      s_x[(qq * 4 + 3) * 516 + r] = v.w;
    }
    __syncthreads();
#pragma unroll
    for (int kk = 0; kk < 32; kk++) {
      float a0 = s_x[kk * 516 + tid];
      float a1 = s_x[kk * 516 + tid + 256];
      float4 w0 = *(const float4*)&s_W[(k0 + kk) * 12];
      float4 w1 = *(const float4*)&s_W[(k0 + kk) * 12 + 4];
      float4 w2 = *(const float4*)&s_W[(k0 + kk) * 12 + 8];
      acc0[0] += a0 * w0.x; acc0[1] += a0 * w0.y; acc0[2]  += a0 * w0.z; acc0[3]  += a0 * w0.w;
      acc0[4] += a0 * w1.x; acc0[5] += a0 * w1.y; acc0[6]  += a0 * w1.z; acc0[7]  += a0 * w1.w;
      acc0[8] += a0 * w2.x; acc0[9] += a0 * w2.y; acc0[10] += a0 * w2.z; acc0[11] += a0 * w2.w;
      acc1[0] += a1 * w0.x; acc1[1] += a1 * w0.y; acc1[2]  += a1 * w0.z; acc1[3]  += a1 * w0.w;
      acc1[4] += a1 * w1.x; acc1[5] += a1 * w1.y; acc1[6]  += a1 * w1.z; acc1[7]  += a1 * w1.w;
      acc1[8] += a1 * w2.x; acc1[9] += a1 * w2.y; acc1[10] += a1 * w2.z; acc1[11] += a1 * w2.w;
    }
  }
#pragma unroll
  for (int h = 0; h < 12; h++) {
    float b = s_b[h];
    size_t base = ((size_t)h * LL1 + i) * LL1 + j0 + tid;
    g_Z[base]       += PAIR_W * (acc0[h] + b);
    g_Z[base + 256] += PAIR_W * (acc1[h] + b);
  }
}

// ------------- K5: fused softmax + r_2d (block = i) -------------
// Stage logits, softmax in smem (write attn back to g_Z), then stream x2d.
__global__ __launch_bounds__(256) void k_smr2d(const float* __restrict__ x2d) {
  __shared__ float s_at[12][1032];
  __shared__ float s_part[128 * 12];
  int i = blockIdx.x, tid = threadIdx.x;
  int lane = tid & 31, w = tid >> 5;
  // stage logits
  for (int idx = tid; idx < 12288; idx += 256) {
    int row = idx >> 10, col = idx & 1023;
    s_at[row][col] = g_Z[((size_t)row * LL1 + i) * LL1 + col];
  }
  __syncthreads();
  // softmax: warp w handles rows w (and w+8 for w<4)
  for (int hh = w; hh < 12; hh += 8) {
    float* row = s_at[hh];
    float m = -3.4e38f;
#pragma unroll
    for (int k = 0; k < 32; k++) m = fmaxf(m, row[k * 32 + lane]);
#pragma unroll
    for (int o = 16; o; o >>= 1) m = fmaxf(m, __shfl_xor_sync(~0u, m, o));
    float s = 0.f;
#pragma unroll
    for (int k = 0; k < 32; k++) {
      float e = __expf(row[k * 32 + lane] - m);
      row[k * 32 + lane] = e;
      s += e;
    }
#pragma unroll
    for (int o = 16; o; o >>= 1) s += __shfl_xor_sync(~0u, s, o);
    float inv = 1.f / s;
    float* zr = &g_Z[((size_t)hh * LL1 + i) * LL1];
#pragma unroll
    for (int k = 0; k < 32; k++) {
      float a = row[k * 32 + lane] * inv;
      row[k * 32 + lane] = a;
      zr[k * 32 + lane] = a;
    }
  }
  __syncthreads();
  // r_2d phase
  int c4 = (tid & 31) * 4;
  int hg = (tid >> 5) & 3;
  int jslab = tid >> 7;
  float4 acc[3] = {};
  const float* xr = x2d + ((size_t)i * LL1 + jslab * 512) * PP + c4;
#pragma unroll 4
  for (int jj = 0; jj < 512; jj++) {
    float4 xv = *(const float4*)(xr + (size_t)jj * PP);
#pragma unroll
    for (int hh = 0; hh < 3; hh++) {
      float a = s_at[hg * 3 + hh][jslab * 512 + jj];
      acc[hh].x += a * xv.x; acc[hh].y += a * xv.y;
      acc[hh].z += a * xv.z; acc[hh].w += a * xv.w;
    }
  }
  if (jslab == 1) {
    int p = tid - 128;
#pragma unroll
    for (int hh = 0; hh < 3; hh++)
      *(float4*)&s_part[(hh * 128 + p) * 4] = acc[hh];
  }
  __syncthreads();
  if (jslab == 0) {
    size_t base = (size_t)i * FEAT + 576;
#pragma unroll
    for (int hh = 0; hh < 3; hh++) {
      float4 o = *(const float4*)&s_part[(hh * 128 + tid) * 4];
      o.x += acc[hh].x; o.y += acc[hh].y; o.z += acc[hh].z; o.w += acc[hh].w;
      *(float4*)&g_feat[base + (hg * 3 + hh) * PP + c4] = o;
    }
  }
}

// ------------- K6: attn @ {v_s, vp} + inverse rigid + f_n -------------
__global__ void k_attnout(const float* __restrict__ rot, const float* __restrict__ trans) {
  int i0 = blockIdx.x * 8, h = blockIdx.y;
  int tid = threadIdx.x, lane = tid & 31, w = tid >> 5;
  __shared__ float s_a[8][1024];
  __shared__ float s_out[40][8];
  for (int idx = tid; idx < 8192; idx += 256) {
    int ii = idx >> 10, j = idx & 1023;
    s_a[ii][j] = g_Z[(size_t)(h * LL1 + i0 + ii) * LL1 + j];
  }
  __syncthreads();
  float acc[5][8];
#pragma unroll
  for (int c = 0; c < 5; c++)
#pragma unroll
    for (int ii = 0; ii < 8; ii++) acc[c][ii] = 0.f;
  const float* vptr[5];
#pragma unroll
  for (int c = 0; c < 5; c++) {
    int ch = w * 5 + c;
    vptr[c] = (ch < 16) ? &g_vT[(h * 16 + ch) * LL1] : &g_vpT[(h * 24 + ch - 16) * LL1];
  }
  for (int j = lane; j < 1024; j += 32) {
    float a[8];
#pragma unroll
    for (int ii = 0; ii < 8; ii++) a[ii] = s_a[ii][j];
#pragma unroll
    for (int c = 0; c < 5; c++) {
      float v = vptr[c][j];
#pragma unroll
      for (int ii = 0; ii < 8; ii++) acc[c][ii] += a[ii] * v;
    }
  }
#pragma unroll
  for (int c = 0; c < 5; c++)
#pragma unroll
    for (int ii = 0; ii < 8; ii++) {
      float s = acc[c][ii];
      for (int o = 16; o; o >>= 1) s += __shfl_xor_sync(~0u, s, o);
      if (lane == 0) s_out[w * 5 + c][ii] = s;
    }
  __syncthreads();
  if (tid < 128) {
    int ii = tid >> 4, c = tid & 15;
    g_feat[(size_t)(i0 + ii) * FEAT + h * 16 + c] = s_out[c][ii];
  } else if (tid < 192) {
    int p = tid - 128, ii = p >> 3, n = p & 7;
    int gi = i0 + ii;
    float R[9], t[3];
#pragma unroll
    for (int q = 0; q < 9; q++) R[q] = rot[gi * 9 + q];
#pragma unroll
    for (int q = 0; q < 3; q++) t[q] = trans[gi * 3 + q];
    float d0 = s_out[16 + n * 3 + 0][ii] - t[0];
    float d1 = s_out[16 + n * 3 + 1][ii] - t[1];
    float d2 = s_out[16 + n * 3 + 2][ii] - t[2];
    float lx = R[0] * d0 + R[3] * d1 + R[6] * d2;
    float ly = R[1] * d0 + R[4] * d1 + R[7] * d2;
    float lz = R[2] * d0 + R[5] * d1 + R[8] * d2;
    size_t base = (size_t)gi * FEAT;
    g_feat[base + 192 + 0 * 96 + h * 8 + n] = lx;
    g_feat[base + 192 + 1 * 96 + h * 8 + n] = ly;
    g_feat[base + 192 + 2 * 96 + h * 8 + n] = lz;
    g_feat[base + 480 + h * 8 + n] = sqrtf(lx * lx + ly * ly + lz * lz + 1e-8f);
  }
}

// ------------- K7: output GEMM, split-K x12 partials -------------
__global__ __launch_bounds__(256) void k_outpart(const float* __restrict__ Wout) {
  __shared__ float s_f[16][68];
  __shared__ float s_w[16][68];
  int tid = threadIdx.x;
  int tx = tid & 15, ty = tid >> 4;
  int i0 = blockIdx.x * 64, c0 = blockIdx.y * 64;
  int kbeg = blockIdx.z * KSLICE, kend = kbeg + KSLICE;
  float acc[4][4] = {};
  for (int k0 = kbeg; k0 < kend; k0 += 16) {
    __syncthreads();
    for (int idx = tid; idx < 1024; idx += 256) {
      int il = idx >> 4, kk = idx & 15;
      s_f[kk][il] = g_feat[(size_t)(i0 + il) * FEAT + k0 + kk];
    }
    for (int idx = tid; idx < 1024; idx += 256) {
      int kk = idx >> 6, cl = idx & 63;
      s_w[kk][cl] = Wout[(size_t)(k0 + kk) * CC + c0 + cl];
    }
    __syncthreads();
#pragma unroll
    for (int kk = 0; kk < 16; kk++) {
      float xv[4], wv[4];
#pragma unroll
      for (int r = 0; r < 4; r++) xv[r] = s_f[kk][ty * 4 + r];
#pragma unroll
      for (int c = 0; c < 4; c++) wv[c] = s_w[kk][tx * 4 + c];
#pragma unroll
      for (int r = 0; r < 4; r++)
#pragma unroll
        for (int c = 0; c < 4; c++) acc[r][c] += xv[r] * wv[c];
    }
  }
  float* part = &g_part[(size_t)blockIdx.z * LL1 * CC];
#pragma unroll
  for (int r = 0; r < 4; r++)
#pragma unroll
    for (int c = 0; c < 4; c++)
      part[(size_t)(i0 + ty * 4 + r) * CC + c0 + tx * 4 + c] = acc[r][c];
}

__global__ __launch_bounds__(256) void k_outadd(const float* __restrict__ bout,
                                                float* __restrict__ out) {
  int idx = blockIdx.x * 256 + threadIdx.x;
  float s = 0.f;
#pragma unroll
  for (int z = 0; z < KSPLIT; z++) s += g_part[(size_t)z * LL1 * CC + idx];
  out[idx] = s + bout[idx % CC];
}

// ------------- launch -------------
extern "C" void kernel_launch(void* const* d_in, const int* in_sizes, int n_in,
                              void* d_out, int out_size) {
  (void)in_sizes; (void)n_in; (void)out_size;
  const float* x1d   = (const float*)d_in[0];
  const float* x2d   = (const float*)d_in[1];
  const float* rot   = (const float*)d_in[2];
  const float* trans = (const float*)d_in[3];
  const float* Wq    = (const float*)d_in[5];
  const float* bq    = (const float*)d_in[6];
  const float* Wkv   = (const float*)d_in[7];
  const float* bkv   = (const float*)d_in[8];
  const float* Wqp   = (const float*)d_in[9];
  const float* bqp   = (const float*)d_in[10];
  const float* Wkvp  = (const float*)d_in[11];
  const float* bkvp  = (const float*)d_in[12];
  const float* Wpair = (const float*)d_in[13];
  const float* bpair = (const float*)d_in[14];
  const float* tpw   = (const float*)d_in[15];
  const float* Wout  = (const float*)d_in[16];
  const float* bout  = (const float*)d_in[17];
  float* out = (float*)d_out;

  cudaFuncSetAttribute(k_pairbias, cudaFuncAttributeMaxDynamicSharedMemorySize, PB_SMEM_BYTES);

  k_projgemm<<<dim3(32, 9), 256>>>(x1d, Wq, Wkv, Wqp, Wkvp);
  k_post<<<1024, 256>>>(rot, trans, bq, bkv, bqp, bkvp);
  k_qk<<<dim3(64, 12), 256>>>(tpw);
  k_pairbias<<<dim3(1024, 2), 256, PB_SMEM_BYTES>>>(x2d, Wpair, bpair);
  k_smr2d<<<1024, 256>>>(x2d);
  k_attnout<<<dim3(128, 12), 256>>>(rot, trans);
  k_outpart<<<dim3(16, 6, KSPLIT), 256>>>(Wout);
  k_outadd<<<1536, 256>>>(bout, out);
}